// round 16
// baseline (speedup 1.0000x reference)
#include <cuda_runtime.h>
#include <math.h>

#define L_SEQ 4096
#define EDIM  512
#define HDIM  1024
#define G3    3072
#define CHUNK 128
#define NCHUNK (L_SEQ / CHUNK)      // 32
#define L0CTA 32
#define L1CTA 32
#define GEMCTA 20
#define NFUSED (L0CTA + L1CTA + GEMCTA)   // 84 CTAs < 148 SMs -> single wave

// ---------------- scratch (static device globals; no allocation) -------------
__device__ float g_emb[(size_t)L_SEQ * EDIM];          // 8 MB
__device__ float g_gi0[(size_t)L_SEQ * G3];            // 50 MB
__device__ float g_gi1[(size_t)L_SEQ * G3];            // 50 MB
__device__ float g_ys [(size_t)L_SEQ * HDIM];          // 16 MB
__device__ float g_h0[2][HDIM];
__device__ float g_h1[2][HDIM];

struct __align__(128) CtrLine { unsigned v; unsigned pad[31]; };
__device__ CtrLine g_ctrA;   // layer-0 step counter  (+32 per tick)
__device__ CtrLine g_ctrB;   // gi1 chunk counter     (+20 per chunk)
__device__ CtrLine g_ctrC;   // layer-1 step counter  (+32 per tick)
__device__ CtrLine g_ctrD;   // gi0 chunk counter     (+20 per chunk)

// ---------------- memory-model helpers ---------------------------------------
__device__ __forceinline__ unsigned ldacq_u32(const unsigned* p)
{
    unsigned v;
    asm volatile("ld.acquire.gpu.global.b32 %0, [%1];" : "=r"(v) : "l"(p) : "memory");
    return v;
}
__device__ __forceinline__ void red_release_add(unsigned* p, unsigned v)
{
    asm volatile("red.release.gpu.global.add.u32 [%0], %1;" :: "l"(p), "r"(v) : "memory");
}
__device__ __forceinline__ float4 ldacq_v4(const float* p)
{
    float4 v;
    asm volatile("ld.acquire.gpu.global.v4.f32 {%0,%1,%2,%3}, [%4];"
                 : "=f"(v.x), "=f"(v.y), "=f"(v.z), "=f"(v.w) : "l"(p) : "memory");
    return v;
}

// ---------------- packed f32x2 helpers (sm_103a) ------------------------------
__device__ __forceinline__ unsigned long long pack2(float x, float y)
{
    unsigned long long r;
    asm("mov.b64 %0, {%1, %2};" : "=l"(r) : "f"(x), "f"(y));
    return r;
}
__device__ __forceinline__ unsigned long long fma2(unsigned long long a,
                                                   unsigned long long b,
                                                   unsigned long long c)
{
    unsigned long long d;
    asm("fma.rn.f32x2 %0, %1, %2, %3;" : "=l"(d) : "l"(a), "l"(b), "l"(c));
    return d;
}
__device__ __forceinline__ float2 unpack2(unsigned long long v)
{
    float2 f;
    asm("mov.b64 {%0, %1}, %2;" : "=f"(f.x), "=f"(f.y) : "l"(v));
    return f;
}

__device__ __forceinline__ float fsig(float x)
{
    return __fdividef(1.0f, 1.0f + __expf(-x));
}
__device__ __forceinline__ float ftanh(float x)
{
    return 1.0f - __fdividef(2.0f, 1.0f + __expf(2.0f * x));
}

// ---------------- embedding + max-norm --------------------------------------
__global__ void embed_kernel(const int* __restrict__ idx,
                             const float* __restrict__ E,
                             float* __restrict__ emb)
{
    int t = blockIdx.x;
    int id = idx[t];
    const float4* row = (const float4*)(E + (size_t)id * EDIM);
    float4 v = row[threadIdx.x];
    float ss = v.x*v.x + v.y*v.y + v.z*v.z + v.w*v.w;
    #pragma unroll
    for (int o = 16; o; o >>= 1) ss += __shfl_xor_sync(0xffffffffu, ss, o);
    __shared__ float red[4];
    int w = threadIdx.x >> 5;
    if ((threadIdx.x & 31) == 0) red[w] = ss;
    __syncthreads();
    float tot = red[0] + red[1] + red[2] + red[3];
    float scale = fminf(1.0f, 1.0f / fmaxf(sqrtf(tot), 1e-7f));
    v.x *= scale; v.y *= scale; v.z *= scale; v.w *= scale;
    ((float4*)(emb + (size_t)t * EDIM))[threadIdx.x] = v;
}

// ---------------- double-buffered f32x2 GEMM tile: 128x128, C = A@B^T + bias --
__device__ void gemm_tile_db(const float* __restrict__ Ab,
                             const float* __restrict__ Bb,
                             const float* __restrict__ bias,
                             float* __restrict__ Cb,
                             int ldc, int K)
{
    __shared__ float As[2][16][128];
    __shared__ float Bs[2][16][136];
    int tid = threadIdx.x;
    int tx = tid & 15, ty = tid >> 4;

    unsigned long long acc2[8][4];
    #pragma unroll
    for (int i = 0; i < 8; i++)
        #pragma unroll
        for (int j = 0; j < 4; j++) acc2[i][j] = 0ull;

    int q0 = tid,        r0 = q0 >> 2, c0 = q0 & 3;
    int q1 = tid + 256,  r1 = q1 >> 2, c1 = q1 & 3;

    float4 ra0, ra1, rb0, rb1;
    ra0 = *(const float4*)(Ab + (size_t)r0 * K + c0 * 4);
    rb0 = *(const float4*)(Bb + (size_t)r0 * K + c0 * 4);
    ra1 = *(const float4*)(Ab + (size_t)r1 * K + c1 * 4);
    rb1 = *(const float4*)(Bb + (size_t)r1 * K + c1 * 4);
    As[0][c0*4+0][r0] = ra0.x; As[0][c0*4+1][r0] = ra0.y; As[0][c0*4+2][r0] = ra0.z; As[0][c0*4+3][r0] = ra0.w;
    Bs[0][c0*4+0][r0] = rb0.x; Bs[0][c0*4+1][r0] = rb0.y; Bs[0][c0*4+2][r0] = rb0.z; Bs[0][c0*4+3][r0] = rb0.w;
    As[0][c1*4+0][r1] = ra1.x; As[0][c1*4+1][r1] = ra1.y; As[0][c1*4+2][r1] = ra1.z; As[0][c1*4+3][r1] = ra1.w;
    Bs[0][c1*4+0][r1] = rb1.x; Bs[0][c1*4+1][r1] = rb1.y; Bs[0][c1*4+2][r1] = rb1.z; Bs[0][c1*4+3][r1] = rb1.w;
    __syncthreads();

    int nb = K / 16;
    for (int kb = 0; kb < nb; kb++) {
        int buf = kb & 1;
        bool more = (kb + 1 < nb);
        if (more) {
            int k0 = (kb + 1) * 16;
            ra0 = *(const float4*)(Ab + (size_t)r0 * K + k0 + c0 * 4);
            rb0 = *(const float4*)(Bb + (size_t)r0 * K + k0 + c0 * 4);
            ra1 = *(const float4*)(Ab + (size_t)r1 * K + k0 + c1 * 4);
            rb1 = *(const float4*)(Bb + (size_t)r1 * K + k0 + c1 * 4);
        }
        #pragma unroll
        for (int k = 0; k < 16; k++) {
            float4 a0 = *(const float4*)&As[buf][k][ty*8];
            float4 a1 = *(const float4*)&As[buf][k][ty*8+4];
            float4 b0 = *(const float4*)&Bs[buf][k][tx*8];
            float4 b1 = *(const float4*)&Bs[buf][k][tx*8+4];
            float av[8] = {a0.x,a0.y,a0.z,a0.w,a1.x,a1.y,a1.z,a1.w};
            unsigned long long bp[4] = { pack2(b0.x,b0.y), pack2(b0.z,b0.w),
                                         pack2(b1.x,b1.y), pack2(b1.z,b1.w) };
            #pragma unroll
            for (int i = 0; i < 8; i++) {
                unsigned long long ad = pack2(av[i], av[i]);
                #pragma unroll
                for (int j = 0; j < 4; j++)
                    acc2[i][j] = fma2(ad, bp[j], acc2[i][j]);
            }
        }
        if (more) {
            int nbuf = (kb + 1) & 1;
            As[nbuf][c0*4+0][r0] = ra0.x; As[nbuf][c0*4+1][r0] = ra0.y; As[nbuf][c0*4+2][r0] = ra0.z; As[nbuf][c0*4+3][r0] = ra0.w;
            Bs[nbuf][c0*4+0][r0] = rb0.x; Bs[nbuf][c0*4+1][r0] = rb0.y; Bs[nbuf][c0*4+2][r0] = rb0.z; Bs[nbuf][c0*4+3][r0] = rb0.w;
            As[nbuf][c1*4+0][r1] = ra1.x; As[nbuf][c1*4+1][r1] = ra1.y; As[nbuf][c1*4+2][r1] = ra1.z; As[nbuf][c1*4+3][r1] = ra1.w;
            Bs[nbuf][c1*4+0][r1] = rb1.x; Bs[nbuf][c1*4+1][r1] = rb1.y; Bs[nbuf][c1*4+2][r1] = rb1.z; Bs[nbuf][c1*4+3][r1] = rb1.w;
            __syncthreads();
        }
    }

    float bb[8];
    #pragma unroll
    for (int j = 0; j < 8; j++) bb[j] = bias[tx*8 + j];
    #pragma unroll
    for (int i = 0; i < 8; i++) {
        size_t row = (size_t)(ty*8 + i);
        float2 e0 = unpack2(acc2[i][0]);
        float2 e1 = unpack2(acc2[i][1]);
        float2 e2 = unpack2(acc2[i][2]);
        float2 e3 = unpack2(acc2[i][3]);
        float4 o0 = make_float4(e0.x+bb[0], e0.y+bb[1], e1.x+bb[2], e1.y+bb[3]);
        float4 o1 = make_float4(e2.x+bb[4], e2.y+bb[5], e3.x+bb[6], e3.y+bb[7]);
        *(float4*)(Cb + row * ldc + tx*8    ) = o0;
        *(float4*)(Cb + row * ldc + tx*8 + 4) = o1;
    }
    __syncthreads();   // smem safe for next tile; orders C stores before release
}

// produce one 128-token chunk of an input projection
__device__ void produce_chunk(int g, const float* A, int K,
                              const float* W, const float* bias,
                              float* C, int ch)
{
    for (int tn = g; tn < G3 / 128; tn += GEMCTA) {
        gemm_tile_db(A + (size_t)(ch * CHUNK) * K,
                     W + (size_t)(tn * 128) * K,
                     bias + tn * 128,
                     C + (size_t)(ch * CHUNK) * G3 + tn * 128,
                     G3, K);
    }
}

// ---------------- fused wavefront kernel --------------------------------------
// CTAs [0,32)   : layer-0 scan (ctrA), gated by ctrD at chunk boundaries
// CTAs [32,64)  : layer-1 scan (ctrC), gated by ctrB at chunk boundaries
// CTAs [64,84)  : GEMM group: pre gi0[0..1]; per ch: gi1[ch], gi0[ch+2]
// Scan: 4 units/warp (quarter-warp per unit); h read ONCE per lane; 3-stage
// split-tree reduction (27 shfl); lanes 0/8/16/24 publish.
__global__ void __launch_bounds__(256, 1) fused_kernel(
    const float* __restrict__ Whh0, const float* __restrict__ bhh0,
    const float* __restrict__ Whh1, const float* __restrict__ bhh1,
    const float* __restrict__ Wih0, const float* __restrict__ bih0,
    const float* __restrict__ Wih1, const float* __restrict__ bih1,
    float* __restrict__ out)
{
    int blk = blockIdx.x;
    int tid = threadIdx.x;

    if (blk >= L0CTA + L1CTA) {
        // ---------------- GEMM group ----------------
        int g = blk - (L0CTA + L1CTA);
        for (int ch = 0; ch < 2; ch++) {
            produce_chunk(g, g_emb, EDIM, Wih0, bih0, g_gi0, ch);
            if (tid == 0) red_release_add(&g_ctrD.v, 1u);
        }
        for (int ch = 0; ch < NCHUNK; ch++) {
            if (tid == 0) {
                unsigned tgt = (unsigned)L0CTA * (unsigned)(CHUNK * (ch + 1));
                while ((int)(ldacq_u32(&g_ctrA.v) - tgt) < 0)
                    __nanosleep(256);          // coarse wait: back off the hot line
            }
            __syncthreads();
            produce_chunk(g, g_ys, HDIM, Wih1, bih1, g_gi1, ch);
            if (tid == 0) red_release_add(&g_ctrB.v, 1u);
            if (ch + 2 < NCHUNK) {
                produce_chunk(g, g_emb, EDIM, Wih0, bih0, g_gi0, ch + 2);
                if (tid == 0) red_release_add(&g_ctrD.v, 1u);
            }
        }
        return;
    }

    // ---------------- scan roles ----------------
    int layer = (blk >= L0CTA) ? 1 : 0;
    int cb    = layer ? blk - L0CTA : blk;
    int w     = tid >> 5;
    int lane  = tid & 31;
    int q     = (lane >> 3) & 3;              // quarter index = which unit
    int u0    = cb * 32 + 4 * w;              // warp owns units u0..u0+3
    int unit  = u0 + q;                       // this quarter-warp's unit

    const float* Whh = layer ? Whh1 : Whh0;
    const float* bhh = layer ? bhh1 : bhh0;
    const float* gi  = layer ? g_gi1 : g_gi0;
    unsigned* stepctr  = layer ? &g_ctrC.v : &g_ctrA.v;
    unsigned* chunkctr = layer ? &g_ctrB.v : &g_ctrD.v;

    // 4 units' weight rows in-lane; lane covers h[c*128+lane*4 .. +4)
    ulonglong2 wr2[4][8], wz2[4][8], wn2[4][8];
    #pragma unroll
    for (int j = 0; j < 4; j++) {
        const ulonglong2* Wr = (const ulonglong2*)(Whh + (size_t)(u0+j)          * HDIM);
        const ulonglong2* Wz = (const ulonglong2*)(Whh + (size_t)(HDIM   + u0+j) * HDIM);
        const ulonglong2* Wn = (const ulonglong2*)(Whh + (size_t)(2*HDIM + u0+j) * HDIM);
        #pragma unroll
        for (int c = 0; c < 8; c++) {
            wr2[j][c] = Wr[c*32 + lane];
            wz2[j][c] = Wz[c*32 + lane];
            wn2[j][c] = Wn[c*32 + lane];
        }
    }
    // per-lane biases for THIS quarter's unit (direct loads)
    float brj = bhh[unit];
    float bzj = bhh[HDIM   + unit];
    float bnj = bhh[2*HDIM + unit];

    __shared__ __align__(16) float h_s[HDIM];
    __shared__ float gi_s[2][96];              // 32 units x 3 gates, double-buffered
    float h_last = 0.0f;

    // gi loader: tid<96 covers [gate=tid>>5][local unit=tid&31]
    size_t gi_off = (size_t)(tid >> 5) * HDIM + cb * 32 + (tid & 31);

    for (int t = 0; t < L_SEQ; t++) {
        bool boundary = (t & (CHUNK - 1)) == 0;
        bool pre_next = ((t + 1) & (CHUNK - 1)) != 0 && (t + 1) < L_SEQ;

        // warp 0: chunk gate (rare) + 4-lane cooperative step poll
        if (w == 0) {
            if (boundary && lane == 0) {
                unsigned tb = (unsigned)GEMCTA * ((unsigned)(t >> 7) + 1u);
                while ((int)(ldacq_u32(chunkctr) - tb) < 0) { }
            }
            __syncwarp();
            unsigned tgt = (unsigned)L0CTA * (unsigned)t;
            for (;;) {
                unsigned v = (lane < 4) ? ldacq_u32(stepctr) : 0u;
                bool sat = (lane < 4) && ((int)(v - tgt) >= 0);
                if (__any_sync(0xffffffffu, sat)) break;
            }
        }
        __syncthreads();                       // bar#1

        if (boundary && tid < 96)
            gi_s[t & 1][tid] = gi[(size_t)t * G3 + gi_off];

        const float* hb = layer ? g_h1[t & 1] : g_h0[t & 1];
        float4 hv = ldacq_v4(hb + tid * 4);
        *(float4*)&h_s[tid * 4] = hv;
        __syncthreads();                       // bar#2

        float gnext = 0.0f;
        if (pre_next && tid < 96)
            gnext = gi[(size_t)(t + 1) * G3 + gi_off];

        // FMA phase: h read ONCE per lane, serves 4 units
        unsigned long long ar2[4], az2[4], an2[4];
        #pragma unroll
        for (int j = 0; j < 4; j++) { ar2[j] = 0ull; az2[j] = 0ull; an2[j] = 0ull; }
        #pragma unroll
        for (int c = 0; c < 8; c++) {
            ulonglong2 h2 = *(const ulonglong2*)&h_s[c*128 + lane*4];
            #pragma unroll
            for (int j = 0; j < 4; j++) {
                ar2[j] = fma2(wr2[j][c].x, h2.x, ar2[j]);
                az2[j] = fma2(wz2[j][c].x, h2.x, az2[j]);
                an2[j] = fma2(wn2[j][c].x, h2.x, an2[j]);
                ar2[j] = fma2(wr2[j][c].y, h2.y, ar2[j]);
                az2[j] = fma2(wz2[j][c].y, h2.y, az2[j]);
                an2[j] = fma2(wn2[j][c].y, h2.y, an2[j]);
            }
        }
        float sR[4], sZ[4], sN[4];
        #pragma unroll
        for (int j = 0; j < 4; j++) {
            float2 f;
            f = unpack2(ar2[j]); sR[j] = f.x + f.y;
            f = unpack2(az2[j]); sZ[j] = f.x + f.y;
            f = unpack2(an2[j]); sN[j] = f.x + f.y;
        }

        // split-tree: L16 on 12 -> half-warp picks its 2 units -> L8 on 6
        //             -> quarter picks its unit -> L4,L2,L1 on 3
        #pragma unroll
        for (int j = 0; j < 4; j++) {
            sR[j] += __shfl_xor_sync(0xffffffffu, sR[j], 16);
            sZ[j] += __shfl_xor_sync(0xffffffffu, sZ[j], 16);
            sN[j] += __shfl_xor_sync(0xffffffffu, sN[j], 16);
        }
        int hi = (lane >> 4) & 1;              // half-warp: units {0,1} vs {2,3}
        float t0r = hi ? sR[2] : sR[0];
        float t0z = hi ? sZ[2] : sZ[0];
        float t0n = hi ? sN[2] : sN[0];
        float t1r = hi ? sR[3] : sR[1];
        float t1z = hi ? sZ[3] : sZ[1];
        float t1n = hi ? sN[3] : sN[1];
        t0r += __shfl_xor_sync(0xffffffffu, t0r, 8);
        t0z += __shfl_xor_sync(0xffffffffu, t0z, 8);
        t0n += __shfl_xor_sync(0xffffffffu, t0n, 8);
        t1r += __shfl_xor_sync(0xffffffffu, t1r, 8);
        t1z += __shfl_xor_sync(0xffffffffu, t1z, 8);
        t1n += __shfl_xor_sync(0xffffffffu, t1n, 8);
        int q3 = (lane >> 3) & 1;              // quarter within half: unit lo/hi
        float sr = q3 ? t1r : t0r;
        float sz = q3 ? t1z : t0z;
        float sn = q3 ? t1n : t0n;
        #pragma unroll
        for (int o = 4; o; o >>= 1) {          // stays within each 8-lane quarter
            sr += __shfl_xor_sync(0xffffffffu, sr, o);
            sz += __shfl_xor_sync(0xffffffffu, sz, o);
            sn += __shfl_xor_sync(0xffffffffu, sn, o);
        }

        if (pre_next && tid < 96)
            gi_s[(t + 1) & 1][tid] = gnext;

        // gates: quarter-warp handles its unit (8 lanes redundant)
        int lidx = 4 * w + q;                  // local unit index 0..31
        float xr = gi_s[t & 1][     lidx];
        float xz = gi_s[t & 1][32 + lidx];
        float xn = gi_s[t & 1][64 + lidx];
        float r = fsig(xr + sr + brj);
        float z = fsig(xz + sz + bzj);
        float n = ftanh(xn + r * (sn + bnj));
        float hp = h_s[unit];
        float hnw = (1.0f - z) * n + z * hp;
        if ((lane & 7) == 0) {                 // lanes 0,8,16,24 publish
            float* hout = layer ? g_h1[(t + 1) & 1] : g_h0[(t + 1) & 1];
            hout[unit] = hnw;
            if (!layer) g_ys[(size_t)t * HDIM + unit] = hnw;
            h_last = hnw;
        }
        __syncthreads();                       // bar#3: h' stores before arrival
        if (tid == 0)
            red_release_add(stepctr, 1u);
    }

    if ((lane & 7) == 0) {
        if (!layer) {                          // h1 -> out[1024:2048]
            out[HDIM + unit] = h_last;
        } else {                               // ys2[-1]=h2 -> out[0:1024]; h2 -> out[2048:3072]
            out[unit]          = h_last;
            out[2*HDIM + unit] = h_last;
        }
    }
}

// reset: h buffers = 0, counters = 0
__global__ void zero_state_kernel()
{
    g_h0[0][threadIdx.x] = 0.0f;
    g_h0[1][threadIdx.x] = 0.0f;
    g_h1[0][threadIdx.x] = 0.0f;
    g_h1[1][threadIdx.x] = 0.0f;
    if (threadIdx.x == 0) {
        g_ctrA.v = 0u;
        g_ctrB.v = 0u;
        g_ctrC.v = 0u;
        g_ctrD.v = 0u;
    }
}

// ---------------- launch -----------------------------------------------------
extern "C" void kernel_launch(void* const* d_in, const int* in_sizes, int n_in,
                              void* d_out, int out_size)
{
    const int*   idx  = (const int*)  d_in[0];
    const float* E    = (const float*)d_in[1];
    const float* Wih0 = (const float*)d_in[2];
    const float* Whh0 = (const float*)d_in[3];
    const float* bih0 = (const float*)d_in[4];
    const float* bhh0 = (const float*)d_in[5];
    const float* Wih1 = (const float*)d_in[6];
    const float* Whh1 = (const float*)d_in[7];
    const float* bih1 = (const float*)d_in[8];
    const float* bhh1 = (const float*)d_in[9];
    float* out = (float*)d_out;

    float *emb;
    cudaGetSymbolAddress((void**)&emb, g_emb);

    // 1) embedding + max-norm
    embed_kernel<<<L_SEQ, 128>>>(idx, E, emb);

    // 2) everything else in one fused wavefront kernel
    zero_state_kernel<<<1, 1024>>>();
    fused_kernel<<<NFUSED, 256>>>(Whh0, bhh0, Whh1, bhh1,
                                  Wih0, bih0, Wih1, bih1, out);
}

// round 17
// speedup vs baseline: 1.5226x; 1.5226x over previous
#include <cuda_runtime.h>
#include <math.h>

#define L_SEQ 4096
#define EDIM  512
#define HDIM  1024
#define G3    3072
#define CHUNK 128
#define NCHUNK (L_SEQ / CHUNK)      // 32
#define L0CTA 64
#define L1CTA 64
#define GEMCTA 20
#define NFUSED (L0CTA + L1CTA + GEMCTA)   // 148 = #SMs -> single wave guaranteed

// ---------------- scratch (static device globals; no allocation) -------------
__device__ float g_emb[(size_t)L_SEQ * EDIM];          // 8 MB
__device__ float g_gi0[(size_t)L_SEQ * G3];            // 50 MB
__device__ float g_gi1[(size_t)L_SEQ * G3];            // 50 MB
__device__ float g_ys [(size_t)L_SEQ * HDIM];          // 16 MB
__device__ float g_h0[2][HDIM];
__device__ float g_h1[2][HDIM];

struct __align__(128) CtrLine { unsigned v; unsigned pad[31]; };
__device__ CtrLine g_ctrA;   // layer-0 step counter  (+64 per tick)
__device__ CtrLine g_ctrB;   // gi1 chunk counter     (+20 per chunk)
__device__ CtrLine g_ctrC;   // layer-1 step counter  (+64 per tick)
__device__ CtrLine g_ctrD;   // gi0 chunk counter     (+20 per chunk)

// ---------------- memory-model helpers ---------------------------------------
__device__ __forceinline__ unsigned ldacq_u32(const unsigned* p)
{
    unsigned v;
    asm volatile("ld.acquire.gpu.global.b32 %0, [%1];" : "=r"(v) : "l"(p) : "memory");
    return v;
}
__device__ __forceinline__ void red_release_add(unsigned* p, unsigned v)
{
    asm volatile("red.release.gpu.global.add.u32 [%0], %1;" :: "l"(p), "r"(v) : "memory");
}
__device__ __forceinline__ float4 ldacq_v4(const float* p)
{
    float4 v;
    asm volatile("ld.acquire.gpu.global.v4.f32 {%0,%1,%2,%3}, [%4];"
                 : "=f"(v.x), "=f"(v.y), "=f"(v.z), "=f"(v.w) : "l"(p) : "memory");
    return v;
}

// ---------------- packed f32x2 helpers (sm_103a) ------------------------------
__device__ __forceinline__ unsigned long long pack2(float x, float y)
{
    unsigned long long r;
    asm("mov.b64 %0, {%1, %2};" : "=l"(r) : "f"(x), "f"(y));
    return r;
}
__device__ __forceinline__ unsigned long long fma2(unsigned long long a,
                                                   unsigned long long b,
                                                   unsigned long long c)
{
    unsigned long long d;
    asm("fma.rn.f32x2 %0, %1, %2, %3;" : "=l"(d) : "l"(a), "l"(b), "l"(c));
    return d;
}
__device__ __forceinline__ float2 unpack2(unsigned long long v)
{
    float2 f;
    asm("mov.b64 {%0, %1}, %2;" : "=f"(f.x), "=f"(f.y) : "l"(v));
    return f;
}

__device__ __forceinline__ float fsig(float x)
{
    return __fdividef(1.0f, 1.0f + __expf(-x));
}
__device__ __forceinline__ float ftanh(float x)
{
    return 1.0f - __fdividef(2.0f, 1.0f + __expf(2.0f * x));
}

// ---------------- embedding + max-norm --------------------------------------
__global__ void embed_kernel(const int* __restrict__ idx,
                             const float* __restrict__ E,
                             float* __restrict__ emb)
{
    int t = blockIdx.x;
    int id = idx[t];
    const float4* row = (const float4*)(E + (size_t)id * EDIM);
    float4 v = row[threadIdx.x];
    float ss = v.x*v.x + v.y*v.y + v.z*v.z + v.w*v.w;
    #pragma unroll
    for (int o = 16; o; o >>= 1) ss += __shfl_xor_sync(0xffffffffu, ss, o);
    __shared__ float red[4];
    int w = threadIdx.x >> 5;
    if ((threadIdx.x & 31) == 0) red[w] = ss;
    __syncthreads();
    float tot = red[0] + red[1] + red[2] + red[3];
    float scale = fminf(1.0f, 1.0f / fmaxf(sqrtf(tot), 1e-7f));
    v.x *= scale; v.y *= scale; v.z *= scale; v.w *= scale;
    ((float4*)(emb + (size_t)t * EDIM))[threadIdx.x] = v;
}

// ---------------- double-buffered f32x2 GEMM tile: 128x128, C = A@B^T + bias --
__device__ void gemm_tile_db(const float* __restrict__ Ab,
                             const float* __restrict__ Bb,
                             const float* __restrict__ bias,
                             float* __restrict__ Cb,
                             int ldc, int K)
{
    __shared__ float As[2][16][128];
    __shared__ float Bs[2][16][136];
    int tid = threadIdx.x;
    int tx = tid & 15, ty = tid >> 4;

    unsigned long long acc2[8][4];
    #pragma unroll
    for (int i = 0; i < 8; i++)
        #pragma unroll
        for (int j = 0; j < 4; j++) acc2[i][j] = 0ull;

    int q0 = tid,        r0 = q0 >> 2, c0 = q0 & 3;
    int q1 = tid + 256,  r1 = q1 >> 2, c1 = q1 & 3;

    float4 ra0, ra1, rb0, rb1;
    ra0 = *(const float4*)(Ab + (size_t)r0 * K + c0 * 4);
    rb0 = *(const float4*)(Bb + (size_t)r0 * K + c0 * 4);
    ra1 = *(const float4*)(Ab + (size_t)r1 * K + c1 * 4);
    rb1 = *(const float4*)(Bb + (size_t)r1 * K + c1 * 4);
    As[0][c0*4+0][r0] = ra0.x; As[0][c0*4+1][r0] = ra0.y; As[0][c0*4+2][r0] = ra0.z; As[0][c0*4+3][r0] = ra0.w;
    Bs[0][c0*4+0][r0] = rb0.x; Bs[0][c0*4+1][r0] = rb0.y; Bs[0][c0*4+2][r0] = rb0.z; Bs[0][c0*4+3][r0] = rb0.w;
    As[0][c1*4+0][r1] = ra1.x; As[0][c1*4+1][r1] = ra1.y; As[0][c1*4+2][r1] = ra1.z; As[0][c1*4+3][r1] = ra1.w;
    Bs[0][c1*4+0][r1] = rb1.x; Bs[0][c1*4+1][r1] = rb1.y; Bs[0][c1*4+2][r1] = rb1.z; Bs[0][c1*4+3][r1] = rb1.w;
    __syncthreads();

    int nb = K / 16;
    for (int kb = 0; kb < nb; kb++) {
        int buf = kb & 1;
        bool more = (kb + 1 < nb);
        if (more) {
            int k0 = (kb + 1) * 16;
            ra0 = *(const float4*)(Ab + (size_t)r0 * K + k0 + c0 * 4);
            rb0 = *(const float4*)(Bb + (size_t)r0 * K + k0 + c0 * 4);
            ra1 = *(const float4*)(Ab + (size_t)r1 * K + k0 + c1 * 4);
            rb1 = *(const float4*)(Bb + (size_t)r1 * K + k0 + c1 * 4);
        }
        #pragma unroll
        for (int k = 0; k < 16; k++) {
            float4 a0 = *(const float4*)&As[buf][k][ty*8];
            float4 a1 = *(const float4*)&As[buf][k][ty*8+4];
            float4 b0 = *(const float4*)&Bs[buf][k][tx*8];
            float4 b1 = *(const float4*)&Bs[buf][k][tx*8+4];
            float av[8] = {a0.x,a0.y,a0.z,a0.w,a1.x,a1.y,a1.z,a1.w};
            unsigned long long bp[4] = { pack2(b0.x,b0.y), pack2(b0.z,b0.w),
                                         pack2(b1.x,b1.y), pack2(b1.z,b1.w) };
            #pragma unroll
            for (int i = 0; i < 8; i++) {
                unsigned long long ad = pack2(av[i], av[i]);
                #pragma unroll
                for (int j = 0; j < 4; j++)
                    acc2[i][j] = fma2(ad, bp[j], acc2[i][j]);
            }
        }
        if (more) {
            int nbuf = (kb + 1) & 1;
            As[nbuf][c0*4+0][r0] = ra0.x; As[nbuf][c0*4+1][r0] = ra0.y; As[nbuf][c0*4+2][r0] = ra0.z; As[nbuf][c0*4+3][r0] = ra0.w;
            Bs[nbuf][c0*4+0][r0] = rb0.x; Bs[nbuf][c0*4+1][r0] = rb0.y; Bs[nbuf][c0*4+2][r0] = rb0.z; Bs[nbuf][c0*4+3][r0] = rb0.w;
            As[nbuf][c1*4+0][r1] = ra1.x; As[nbuf][c1*4+1][r1] = ra1.y; As[nbuf][c1*4+2][r1] = ra1.z; As[nbuf][c1*4+3][r1] = ra1.w;
            Bs[nbuf][c1*4+0][r1] = rb1.x; Bs[nbuf][c1*4+1][r1] = rb1.y; Bs[nbuf][c1*4+2][r1] = rb1.z; Bs[nbuf][c1*4+3][r1] = rb1.w;
            __syncthreads();
        }
    }

    float bb[8];
    #pragma unroll
    for (int j = 0; j < 8; j++) bb[j] = bias[tx*8 + j];
    #pragma unroll
    for (int i = 0; i < 8; i++) {
        size_t row = (size_t)(ty*8 + i);
        float2 e0 = unpack2(acc2[i][0]);
        float2 e1 = unpack2(acc2[i][1]);
        float2 e2 = unpack2(acc2[i][2]);
        float2 e3 = unpack2(acc2[i][3]);
        float4 o0 = make_float4(e0.x+bb[0], e0.y+bb[1], e1.x+bb[2], e1.y+bb[3]);
        float4 o1 = make_float4(e2.x+bb[4], e2.y+bb[5], e3.x+bb[6], e3.y+bb[7]);
        *(float4*)(Cb + row * ldc + tx*8    ) = o0;
        *(float4*)(Cb + row * ldc + tx*8 + 4) = o1;
    }
    __syncthreads();   // smem safe for next tile; orders C stores before release
}

// produce one 128-token chunk of an input projection
__device__ void produce_chunk(int g, const float* A, int K,
                              const float* W, const float* bias,
                              float* C, int ch)
{
    for (int tn = g; tn < G3 / 128; tn += GEMCTA) {
        gemm_tile_db(A + (size_t)(ch * CHUNK) * K,
                     W + (size_t)(tn * 128) * K,
                     bias + tn * 128,
                     C + (size_t)(ch * CHUNK) * G3 + tn * 128,
                     G3, K);
    }
}

// ---------------- fused wavefront kernel --------------------------------------
// CTAs [0,64)    : layer-0 scan (ctrA), gated by ctrD at chunk boundaries
// CTAs [64,128)  : layer-1 scan (ctrC), gated by ctrB at chunk boundaries
// CTAs [128,148) : GEMM group (nanosleep backoff on coarse ctrA waits)
// Scan: R15 + rotated-chunk FMA (own chunk from registers BEFORE bar#2 ->
// staging/barrier latency hidden behind 12 FMA2s).
__global__ void __launch_bounds__(256, 1) fused_kernel(
    const float* __restrict__ Whh0, const float* __restrict__ bhh0,
    const float* __restrict__ Whh1, const float* __restrict__ bhh1,
    const float* __restrict__ Wih0, const float* __restrict__ bih0,
    const float* __restrict__ Wih1, const float* __restrict__ bih1,
    float* __restrict__ out)
{
    int blk = blockIdx.x;
    int tid = threadIdx.x;

    if (blk >= L0CTA + L1CTA) {
        // ---------------- GEMM group ----------------
        int g = blk - (L0CTA + L1CTA);
        for (int ch = 0; ch < 2; ch++) {
            produce_chunk(g, g_emb, EDIM, Wih0, bih0, g_gi0, ch);
            if (tid == 0) red_release_add(&g_ctrD.v, 1u);
        }
        for (int ch = 0; ch < NCHUNK; ch++) {
            if (tid == 0) {
                unsigned tgt = 64u * (unsigned)(CHUNK * (ch + 1));
                while ((int)(ldacq_u32(&g_ctrA.v) - tgt) < 0)
                    __nanosleep(256);          // back off the hottest line
            }
            __syncthreads();
            produce_chunk(g, g_ys, HDIM, Wih1, bih1, g_gi1, ch);
            if (tid == 0) red_release_add(&g_ctrB.v, 1u);
            if (ch + 2 < NCHUNK) {
                produce_chunk(g, g_emb, EDIM, Wih0, bih0, g_gi0, ch + 2);
                if (tid == 0) red_release_add(&g_ctrD.v, 1u);
            }
        }
        return;
    }

    // ---------------- scan roles ----------------
    int layer = (blk >= L0CTA) ? 1 : 0;
    int cb    = layer ? blk - L0CTA : blk;
    int w     = tid >> 5;
    int lane  = tid & 31;
    int jj    = lane >> 4;                    // which unit of the pair (gates)
    int u0    = cb * 16 + 2 * w;              // warp owns units u0, u0+1
    int unit  = u0 + jj;                      // this half-warp's unit (gates)

    const float* Whh = layer ? Whh1 : Whh0;
    const float* bhh = layer ? bhh1 : bhh0;
    const float* gi  = layer ? g_gi1 : g_gi0;
    unsigned* stepctr  = layer ? &g_ctrC.v : &g_ctrA.v;
    unsigned* chunkctr = layer ? &g_ctrB.v : &g_ctrD.v;

    // ROTATED weight layout: slot i holds chunk (w+i)&7, so slot 0 is the
    // chunk this warp itself stages (available in registers pre-barrier).
    ulonglong2 wr2[2][8], wz2[2][8], wn2[2][8];
    #pragma unroll
    for (int j = 0; j < 2; j++) {
        const ulonglong2* Wr = (const ulonglong2*)(Whh + (size_t)(u0+j)          * HDIM);
        const ulonglong2* Wz = (const ulonglong2*)(Whh + (size_t)(HDIM   + u0+j) * HDIM);
        const ulonglong2* Wn = (const ulonglong2*)(Whh + (size_t)(2*HDIM + u0+j) * HDIM);
        #pragma unroll
        for (int i = 0; i < 8; i++) {
            int c = (w + i) & 7;
            wr2[j][i] = Wr[c*32 + lane];
            wz2[j][i] = Wz[c*32 + lane];
            wn2[j][i] = Wn[c*32 + lane];
        }
    }
    float brj = bhh[unit];
    float bzj = bhh[HDIM   + unit];
    float bnj = bhh[2*HDIM + unit];

    __shared__ __align__(16) float h_s[HDIM];
    __shared__ float gi_s[2][48];              // double-buffered (pipelined)
    float h_last = 0.0f;

    size_t gi_off = (size_t)(tid >> 4) * HDIM + cb * 16 + (tid & 15);

    for (int t = 0; t < L_SEQ; t++) {
        bool boundary = (t & (CHUNK - 1)) == 0;
        bool pre_next = ((t + 1) & (CHUNK - 1)) != 0 && (t + 1) < L_SEQ;

        // warp 0: chunk gate (rare) + 4-lane cooperative step poll
        if (w == 0) {
            if (boundary && lane == 0) {
                unsigned tb = (unsigned)GEMCTA * ((unsigned)(t >> 7) + 1u);
                while ((int)(ldacq_u32(chunkctr) - tb) < 0) { }
            }
            __syncwarp();
            unsigned tgt = 64u * (unsigned)t;
            for (;;) {
                unsigned v = (lane < 4) ? ldacq_u32(stepctr) : 0u;
                bool sat = (lane < 4) && ((int)(v - tgt) >= 0);
                if (__any_sync(0xffffffffu, sat)) break;
            }
        }
        __syncthreads();                       // bar#1

        if (boundary && tid < 48)
            gi_s[t & 1][tid] = gi[(size_t)t * G3 + gi_off];

        // stage own chunk (chunk w): global -> registers -> smem
        const float* hb = layer ? g_h1[t & 1] : g_h0[t & 1];
        float4 hv = ldacq_v4(hb + tid * 4);    // h[w*128 + lane*4 ..)
        *(float4*)&h_s[tid * 4] = hv;

        // FMA slot 0 = own chunk, straight from registers (overlaps others' STS)
        unsigned long long ar2[2], az2[2], an2[2];
        {
            unsigned long long ha = pack2(hv.x, hv.y);
            unsigned long long hbp = pack2(hv.z, hv.w);
            #pragma unroll
            for (int j = 0; j < 2; j++) {
                ar2[j] = fma2(wr2[j][0].x, ha, 0ull);
                az2[j] = fma2(wz2[j][0].x, ha, 0ull);
                an2[j] = fma2(wn2[j][0].x, ha, 0ull);
                ar2[j] = fma2(wr2[j][0].y, hbp, ar2[j]);
                az2[j] = fma2(wz2[j][0].y, hbp, az2[j]);
                an2[j] = fma2(wn2[j][0].y, hbp, an2[j]);
            }
        }
        __syncthreads();                       // bar#2 (all staging visible)

        float gnext = 0.0f;
        if (pre_next && tid < 48)
            gnext = gi[(size_t)(t + 1) * G3 + gi_off];

        // FMA slots 1..7: remaining chunks from smem (rotated addressing)
        #pragma unroll
        for (int i = 1; i < 8; i++) {
            int c = (w + i) & 7;
            ulonglong2 h2 = *(const ulonglong2*)&h_s[c*128 + lane*4];
            #pragma unroll
            for (int j = 0; j < 2; j++) {
                ar2[j] = fma2(wr2[j][i].x, h2.x, ar2[j]);
                az2[j] = fma2(wz2[j][i].x, h2.x, az2[j]);
                an2[j] = fma2(wn2[j][i].x, h2.x, an2[j]);
                ar2[j] = fma2(wr2[j][i].y, h2.y, ar2[j]);
                az2[j] = fma2(wz2[j][i].y, h2.y, az2[j]);
                an2[j] = fma2(wn2[j][i].y, h2.y, an2[j]);
            }
        }
        float2 f;
        f = unpack2(ar2[0]); float s0r = f.x + f.y;
        f = unpack2(az2[0]); float s0z = f.x + f.y;
        f = unpack2(an2[0]); float s0n = f.x + f.y;
        f = unpack2(ar2[1]); float s1r = f.x + f.y;
        f = unpack2(az2[1]); float s1z = f.x + f.y;
        f = unpack2(an2[1]); float s1n = f.x + f.y;

        // split-tree reduction: level 16 on all 6, then half-warps specialize
        s0r += __shfl_xor_sync(0xffffffffu, s0r, 16);
        s0z += __shfl_xor_sync(0xffffffffu, s0z, 16);
        s0n += __shfl_xor_sync(0xffffffffu, s0n, 16);
        s1r += __shfl_xor_sync(0xffffffffu, s1r, 16);
        s1z += __shfl_xor_sync(0xffffffffu, s1z, 16);
        s1n += __shfl_xor_sync(0xffffffffu, s1n, 16);
        float sr = jj ? s1r : s0r;
        float sz = jj ? s1z : s0z;
        float sn = jj ? s1n : s0n;
        #pragma unroll
        for (int o = 8; o; o >>= 1) {          // stays within each half-warp
            sr += __shfl_xor_sync(0xffffffffu, sr, o);
            sz += __shfl_xor_sync(0xffffffffu, sz, o);
            sn += __shfl_xor_sync(0xffffffffu, sn, o);
        }

        if (pre_next && tid < 48)
            gi_s[(t + 1) & 1][tid] = gnext;

        // gates: half-warp handles its unit
        float xr = gi_s[t & 1][      2*w + jj];
        float xz = gi_s[t & 1][16 +  2*w + jj];
        float xn = gi_s[t & 1][32 +  2*w + jj];
        float r = fsig(xr + sr + brj);
        float z = fsig(xz + sz + bzj);
        float n = ftanh(xn + r * (sn + bnj));
        float hp = h_s[unit];
        float hnw = (1.0f - z) * n + z * hp;
        if ((lane & 15) == 0) {                // lanes 0 and 16 publish
            float* hout = layer ? g_h1[(t + 1) & 1] : g_h0[(t + 1) & 1];
            hout[unit] = hnw;
            if (!layer) g_ys[(size_t)t * HDIM + unit] = hnw;
            h_last = hnw;
        }
        __syncthreads();                       // bar#3: stores + gi stage visible
        if (tid == 0)
            red_release_add(stepctr, 1u);
    }

    if ((lane & 15) == 0) {
        if (!layer) {                          // h1 -> out[1024:2048]
            out[HDIM + unit] = h_last;
        } else {                               // ys2[-1]=h2 -> out[0:1024]; h2 -> out[2048:3072]
            out[unit]          = h_last;
            out[2*HDIM + unit] = h_last;
        }
    }
}

// reset: h buffers = 0, counters = 0
__global__ void zero_state_kernel()
{
    g_h0[0][threadIdx.x] = 0.0f;
    g_h0[1][threadIdx.x] = 0.0f;
    g_h1[0][threadIdx.x] = 0.0f;
    g_h1[1][threadIdx.x] = 0.0f;
    if (threadIdx.x == 0) {
        g_ctrA.v = 0u;
        g_ctrB.v = 0u;
        g_ctrC.v = 0u;
        g_ctrD.v = 0u;
    }
}

// ---------------- launch -----------------------------------------------------
extern "C" void kernel_launch(void* const* d_in, const int* in_sizes, int n_in,
                              void* d_out, int out_size)
{
    const int*   idx  = (const int*)  d_in[0];
    const float* E    = (const float*)d_in[1];
    const float* Wih0 = (const float*)d_in[2];
    const float* Whh0 = (const float*)d_in[3];
    const float* bih0 = (const float*)d_in[4];
    const float* bhh0 = (const float*)d_in[5];
    const float* Wih1 = (const float*)d_in[6];
    const float* Whh1 = (const float*)d_in[7];
    const float* bih1 = (const float*)d_in[8];
    const float* bhh1 = (const float*)d_in[9];
    float* out = (float*)d_out;

    float *emb;
    cudaGetSymbolAddress((void**)&emb, g_emb);

    // 1) embedding + max-norm
    embed_kernel<<<L_SEQ, 128>>>(idx, E, emb);

    // 2) everything else in one fused wavefront kernel
    zero_state_kernel<<<1, 1024>>>();
    fused_kernel<<<NFUSED, 256>>>(Whh0, bhh0, Whh1, bhh1,
                                  Wih0, bih0, Wih1, bih1, out);
}